// round 1
// baseline (speedup 1.0000x reference)
#include <cuda_runtime.h>

// ---------------------------------------------------------------------------
// GIN: out = log_softmax( agg2(h2) @ W3 + b3 )
//   h1  = relu( agg1(x) @ W1 + b1 )
//   h2  = relu( BN( h1 @ W2 + b2 ) )
//   aggK(v)_i = v_i + sum_{e: dst(e)=i} v_{src(e)}
// Linear trick: agg(v) @ W = v@W + segsum((v@W)[src]) -> project BEFORE scatter.
// ---------------------------------------------------------------------------

#define N_NODES_MAX 50000

// Scratch (device globals — no allocation allowed in kernel_launch)
__device__ __align__(16) float g_y   [N_NODES_MAX * 16];  // x @ W1
__device__ __align__(16) float g_agg1[N_NODES_MAX * 16];  // y + segsum(y[src])
__device__ __align__(16) float g_w   [N_NODES_MAX * 12];  // h2 @ W3 (10 used, pad 12)
__device__ __align__(16) float g_agg2[N_NODES_MAX * 12];  // w + segsum(w[src])
__device__ int g_idx64;                                   // 1 if edge_index is int64

// ---------------------------------------------------------------------------
// k0: detect edge_index dtype. If int64 (values < 50000 << 2^31), every odd
// 32-bit word is 0. If int32, odd words are random node ids (P[all 0] ~ 0).
// ---------------------------------------------------------------------------
__global__ void k0_detect(const int* __restrict__ ei_words) {
    if (threadIdx.x == 0 && blockIdx.x == 0) {
        int any = 0;
        #pragma unroll 8
        for (int i = 1; i < 512; i += 2) any |= ei_words[i];
        g_idx64 = (any == 0) ? 1 : 0;
    }
}

__device__ __forceinline__ void load_edge(const void* ei, int e, int E, int& src, int& dst) {
    if (g_idx64) {
        const long long* p = (const long long*)ei;
        src = (int)p[e];
        dst = (int)p[E + e];
    } else {
        const int* p = (const int*)ei;
        src = p[e];
        dst = p[E + e];
    }
}

__device__ __forceinline__ void red_add_v4(float* addr, float4 v) {
    asm volatile("red.global.add.v4.f32 [%0], {%1,%2,%3,%4};"
                 :: "l"(addr), "f"(v.x), "f"(v.y), "f"(v.z), "f"(v.w)
                 : "memory");
}

// ---------------------------------------------------------------------------
// k1: y[n][j] = sum_k x[n][k] * W1[k][j]    (64 -> 16), agg1 init = y
// 16 threads per node; W1 in smem (broadcast reads).
// ---------------------------------------------------------------------------
__global__ void k1_proj64to16(const float* __restrict__ x,
                              const float* __restrict__ W1, int N) {
    __shared__ float sW[64 * 16];
    for (int i = threadIdx.x; i < 64 * 16; i += blockDim.x) sW[i] = W1[i];
    __syncthreads();

    int gid = blockIdx.x * blockDim.x + threadIdx.x;
    int n = gid >> 4;
    int j = gid & 15;
    if (n >= N) return;

    const float4* x4 = (const float4*)x + n * 16;
    float acc = 0.0f;
    #pragma unroll
    for (int q = 0; q < 16; q++) {
        float4 xv = x4[q];
        int k = 4 * q;
        acc += xv.x * sW[(k + 0) * 16 + j];
        acc += xv.y * sW[(k + 1) * 16 + j];
        acc += xv.z * sW[(k + 2) * 16 + j];
        acc += xv.w * sW[(k + 3) * 16 + j];
    }
    g_y[n * 16 + j]    = acc;
    g_agg1[n * 16 + j] = acc;   // agg init with self term
}

// ---------------------------------------------------------------------------
// k2: agg1[dst] += y[src]   (16 floats/edge, 4 threads/edge, red.v4)
// ---------------------------------------------------------------------------
__global__ void k2_scatter16(const void* __restrict__ ei, int E) {
    int t = blockIdx.x * blockDim.x + threadIdx.x;
    int e = t >> 2;
    int c = t & 3;
    if (e >= E) return;
    int src, dst;
    load_edge(ei, e, E, src, dst);
    float4 v = ((const float4*)g_y)[src * 4 + c];
    red_add_v4(&g_agg1[dst * 16 + c * 4], v);
}

// ---------------------------------------------------------------------------
// k3: per node: h1 = relu(agg1 + b1); h2 = relu(BN(h1@W2 + b2));
//     w = h2 @ W3 (16->10, pad 12); agg2 init = w.
// BN folded: W2'[k][j] = W2[k][j]*s[j],  b2' = (b2-mean)*s + beta,
//            s[j] = gamma[j]*rsqrt(var[j]+eps)
// ---------------------------------------------------------------------------
__global__ void k3_mlp(const float* __restrict__ b1, const float* __restrict__ W2,
                       const float* __restrict__ b2, const float* __restrict__ gamma,
                       const float* __restrict__ beta, const float* __restrict__ mean,
                       const float* __restrict__ var, const float* __restrict__ W3,
                       int N) {
    __shared__ float sS[16], sB1[16], sB2[16], sW2[256], sW3[160];
    int tid = threadIdx.x;
    if (tid < 16) {
        float s = gamma[tid] * rsqrtf(var[tid] + 1e-5f);
        sS[tid]  = s;
        sB1[tid] = b1[tid];
        sB2[tid] = (b2[tid] - mean[tid]) * s + beta[tid];
    }
    __syncthreads();
    for (int i = tid; i < 256; i += blockDim.x) sW2[i] = W2[i] * sS[i & 15];
    for (int i = tid; i < 160; i += blockDim.x) sW3[i] = W3[i];
    __syncthreads();

    int n = blockIdx.x * blockDim.x + tid;
    if (n >= N) return;

    float h[16];
    const float4* a4 = (const float4*)g_agg1 + n * 4;
    #pragma unroll
    for (int q = 0; q < 4; q++) {
        float4 v = a4[q];
        h[4*q+0] = fmaxf(v.x + sB1[4*q+0], 0.0f);
        h[4*q+1] = fmaxf(v.y + sB1[4*q+1], 0.0f);
        h[4*q+2] = fmaxf(v.z + sB1[4*q+2], 0.0f);
        h[4*q+3] = fmaxf(v.w + sB1[4*q+3], 0.0f);
    }

    float t[16];
    #pragma unroll
    for (int j = 0; j < 16; j++) {
        float acc = sB2[j];
        #pragma unroll
        for (int k = 0; k < 16; k++) acc += h[k] * sW2[k * 16 + j];
        t[j] = fmaxf(acc, 0.0f);
    }

    float wv[12];
    #pragma unroll
    for (int j = 0; j < 10; j++) {
        float acc = 0.0f;
        #pragma unroll
        for (int k = 0; k < 16; k++) acc += t[k] * sW3[k * 10 + j];
        wv[j] = acc;
    }
    wv[10] = 0.0f; wv[11] = 0.0f;

    float4* w4 = (float4*)g_w    + n * 3;
    float4* a2 = (float4*)g_agg2 + n * 3;
    #pragma unroll
    for (int q = 0; q < 3; q++) {
        float4 v = make_float4(wv[4*q], wv[4*q+1], wv[4*q+2], wv[4*q+3]);
        w4[q] = v;
        a2[q] = v;
    }
}

// ---------------------------------------------------------------------------
// k4: agg2[dst] += w[src]   (12 floats/edge, 3 threads/edge, red.v4)
// ---------------------------------------------------------------------------
__global__ void k4_scatter12(const void* __restrict__ ei, int E) {
    int t = blockIdx.x * blockDim.x + threadIdx.x;
    int e = t / 3;
    int c = t - 3 * e;
    if (e >= E) return;
    int src, dst;
    load_edge(ei, e, E, src, dst);
    float4 v = ((const float4*)g_w)[src * 3 + c];
    red_add_v4(&g_agg2[dst * 12 + c * 4], v);
}

// ---------------------------------------------------------------------------
// k5: logits = agg2[:, :10] + b3 ; out = log_softmax(logits)
// ---------------------------------------------------------------------------
__global__ void k5_logsoftmax(const float* __restrict__ b3,
                              float* __restrict__ out, int N) {
    int n = blockIdx.x * blockDim.x + threadIdx.x;
    if (n >= N) return;
    const float4* a = (const float4*)g_agg2 + n * 3;
    float4 v0 = a[0], v1 = a[1], v2 = a[2];
    float v[10];
    v[0] = v0.x + __ldg(&b3[0]);
    v[1] = v0.y + __ldg(&b3[1]);
    v[2] = v0.z + __ldg(&b3[2]);
    v[3] = v0.w + __ldg(&b3[3]);
    v[4] = v1.x + __ldg(&b3[4]);
    v[5] = v1.y + __ldg(&b3[5]);
    v[6] = v1.z + __ldg(&b3[6]);
    v[7] = v1.w + __ldg(&b3[7]);
    v[8] = v2.x + __ldg(&b3[8]);
    v[9] = v2.y + __ldg(&b3[9]);

    float m = v[0];
    #pragma unroll
    for (int j = 1; j < 10; j++) m = fmaxf(m, v[j]);
    float s = 0.0f;
    #pragma unroll
    for (int j = 0; j < 10; j++) s += expf(v[j] - m);
    float lse = m + logf(s);
    float* o = out + n * 10;
    #pragma unroll
    for (int j = 0; j < 10; j++) o[j] = v[j] - lse;
}

// ---------------------------------------------------------------------------
extern "C" void kernel_launch(void* const* d_in, const int* in_sizes, int n_in,
                              void* d_out, int out_size) {
    const float* x     = (const float*)d_in[0];
    const void*  ei    = d_in[1];                 // int64 or int32 (probed)
    const float* W1    = (const float*)d_in[2];
    const float* b1    = (const float*)d_in[3];
    const float* W2    = (const float*)d_in[4];
    const float* b2    = (const float*)d_in[5];
    const float* gamma = (const float*)d_in[6];
    const float* beta  = (const float*)d_in[7];
    const float* mean  = (const float*)d_in[8];
    const float* var   = (const float*)d_in[9];
    const float* W3    = (const float*)d_in[10];
    const float* b3    = (const float*)d_in[11];

    int N = in_sizes[0] / 64;   // 50000
    int E = in_sizes[1] / 2;    // 800000 (element count is dtype-independent)

    k0_detect<<<1, 32>>>((const int*)ei);
    k1_proj64to16<<<(N * 16 + 255) / 256, 256>>>(x, W1, N);
    k2_scatter16<<<(E * 4 + 255) / 256, 256>>>(ei, E);
    k3_mlp<<<(N + 255) / 256, 256>>>(b1, W2, b2, gamma, beta, mean, var, W3, N);
    k4_scatter12<<<(E * 3 + 255) / 256, 256>>>(ei, E);
    k5_logsoftmax<<<(N + 255) / 256, 256>>>(b3, (float*)d_out, N);
}